// round 15
// baseline (speedup 1.0000x reference)
#include <cuda_runtime.h>
#include <cstdint>

// Bandpass biquad (HP1 x LP1), B=128 rows, T=262144. Exact block-level scan
// (R11 math). Per-WARP fill + wait (each warp cp.asyncs its own 1024-word
// segment; warp 0 adds the 260-word history region; warps>=1 a private 16B
// boundary slot), so pass1 starts without a block-wide barrier. Only the scan
// exchange uses __syncthreads. Streaming stores on drain.
// Fix vs R14: bnd placed 16B-aligned (directly after s_in), scF after it.

static constexpr int BLOCK = 128;
static constexpr int CH    = 32;                  // owned samples / thread
static constexpr int NHIST = 8;                   // 8*32 = 256-sample history
static constexpr int SPAN  = BLOCK * CH;          // 4096
static constexpr int PRE   = NHIST * CH + 4;      // 260
static constexpr int IN_WORDS = SPAN + PRE;       // 4356 (x4 = 17424, 16B-aligned)
static constexpr int NWARP = BLOCK / 32;          // 4
// layout: s_in[IN_WORDS] | bnd[NWARP][4] (16B-aligned) | scF[(NWARP+1) float2]
static constexpr int BND_OFF = IN_WORDS;                       // float index
static constexpr int SCF_OFF = IN_WORDS + NWARP * 4;           // float index
static constexpr int SMEM_BYTES = (SCF_OFF + 2 * (NWARP + 1)) * 4;

// 16B-granular bank swizzle for stride-32 accesses (pure permutation).
#define SW(w) ((w) ^ ((((w) >> 5) & 7) << 2))

struct M2 { float a, b, c, d; };                  // [[a,b],[c,d]]
__device__ __forceinline__ M2 msq(M2 m) {
    M2 r;
    r.a = fmaf(m.a, m.a, m.b * m.c);
    r.b = fmaf(m.a, m.b, m.b * m.d);
    r.c = fmaf(m.c, m.a, m.d * m.c);
    r.d = fmaf(m.c, m.b, m.d * m.d);
    return r;
}
__device__ __forceinline__ M2 mmul(M2 p, M2 q) {  // p*q
    M2 r;
    r.a = fmaf(p.a, q.a, p.b * q.c);
    r.b = fmaf(p.a, q.b, p.b * q.d);
    r.c = fmaf(p.c, q.a, p.d * q.c);
    r.d = fmaf(p.c, q.b, p.d * q.d);
    return r;
}

__device__ __forceinline__ void cpa16(uint32_t daddr, const void* src) {
    asm volatile("cp.async.cg.shared.global [%0], [%1], 16;\n"
                 :: "r"(daddr), "l"(src) : "memory");
}

__global__ __launch_bounds__(BLOCK)
void bandpass_kernel(const float* __restrict__ x,
                     const float* __restrict__ p_cf,
                     const float* __restrict__ p_bw,
                     const float* __restrict__ p_gain,
                     const int*   __restrict__ p_sr,
                     float* __restrict__ out,
                     int T, int blocks_per_row)
{
    extern __shared__ float smem[];
    float*  __restrict__ s_in = smem;                          // IN_WORDS
    float*  __restrict__ bnd  = smem + BND_OFF;                // [NWARP][4], 16B-aligned
    float2* __restrict__ scF  = (float2*)(smem + SCF_OFF);     // [0..3]=warp agg, [4]=s_blk
    const uint32_t smem_cvta = (uint32_t)__cvta_generic_to_shared(smem);
    const uint32_t bnd_cvta  = (uint32_t)__cvta_generic_to_shared(bnd);

    const int tid  = threadIdx.x;
    const int lane = tid & 31;
    const int warp = tid >> 5;
    const int row  = blockIdx.x / blocks_per_row;
    const int sblk = blockIdx.x - row * blocks_per_row;
    const int S0   = sblk * SPAN;

    const float* __restrict__ xr   = x   + (size_t)row * T;
    float* __restrict__       orow = out + (size_t)row * T;

    // ---- per-warp fill: warp w cp.asyncs its own 1024-word segment ----
    {
        const int segbase = PRE + warp * 1024;                 // logical word
        #pragma unroll
        for (int m = 0; m < 8; m++) {
            const int w4 = segbase + 4 * (m * 32 + lane);
            cpa16(smem_cvta + 4u * (uint32_t)SW(w4), xr + (S0 - PRE + w4));
        }
        if (warp == 0) {
            // history region [0, PRE) = 65 float4s (zeros before row start)
            #pragma unroll
            for (int m = 0; m < 3; m++) {
                const int idx = m * 32 + lane;
                if (idx < PRE / 4) {
                    const int w4 = 4 * idx;
                    const int e  = S0 - PRE + w4;
                    const uint32_t daddr = smem_cvta + 4u * (uint32_t)SW(w4);
                    if (e >= 0) {
                        cpa16(daddr, xr + e);
                    } else {
                        asm volatile("st.shared.v4.b32 [%0], {%1,%1,%1,%1};"
                                     :: "r"(daddr), "r"(0) : "memory");
                    }
                }
            }
        } else if (lane == 0) {
            // private boundary copy: gmem [S0 + 1024*warp - 4, S0 + 1024*warp)
            cpa16(bnd_cvta + 16u * (uint32_t)warp, xr + (S0 + 1024 * warp - 4));
        }
        asm volatile("cp.async.commit_group;" ::: "memory");
    }

    // ---- coefficients while the fill flies ----
    const float cf   = *p_cf;
    const float bw   = *p_bw;
    const float gain = *p_gain;
    const float nyq  = 0.5f * (float)(*p_sr);
    const float PI_  = 3.14159265358979323846f;

    const float Kh  = tanf(PI_ * ((cf - 0.5f * bw) / nyq) * 0.5f);
    const float ah1 = (Kh - 1.0f) / (Kh + 1.0f);
    const float bh0 = 1.0f / (Kh + 1.0f);
    const float Kl  = tanf(PI_ * ((cf + 0.5f * bw) / nyq) * 0.5f);
    const float al1 = (Kl - 1.0f) / (Kl + 1.0f);
    const float bl0 = Kl / (Kl + 1.0f);

    const float na1 = -(ah1 + al1);   // y = na1*y1 + na2*y2 + gg*(x - x2)
    const float na2 = -(ah1 * al1);
    const float gg  = bh0 * bl0 * gain;

    M2 A32; { M2 A; A.a = na1; A.b = na2; A.c = 1.0f; A.d = 0.0f;
              A32 = msq(A); A32 = msq(A32); A32 = msq(A32);
              A32 = msq(A32); A32 = msq(A32); }

    // ---- per-warp wait: only THIS warp's copies must have landed ----
    asm volatile("cp.async.wait_group 0;" ::: "memory");
    __syncwarp();

    // one zero-y-state filter step (exact x history)
    #define P1_STEP(XC, PJ)                           \
        {                                             \
            float u_  = gg * ((XC) - x_2);            \
            float t0_ = fmaf(na2, y_2, u_);           \
            float yn_ = fmaf(na1, y_1, t0_);          \
            x_2 = x_1; x_1 = (XC);                    \
            y_2 = y_1; y_1 = yn_;                     \
            (PJ) = yn_;                               \
        }

    // ---- pass 1: particular solution of own chunk, zero incoming y-state ----
    float p[CH];
    float2 f;
    {
        const int base = PRE + tid * CH;
        float x_1, x_2;
        if (lane == 0 && warp != 0) {                 // boundary from private copy
            x_1 = bnd[warp * 4 + 3];
            x_2 = bnd[warp * 4 + 2];
        } else {                                      // in own warp's fill range
            x_1 = s_in[SW(base - 1)];
            x_2 = s_in[SW(base - 2)];
        }
        float y_1 = 0.0f, y_2 = 0.0f;
        #pragma unroll
        for (int j = 0; j < CH; j += 4) {
            float4 v = *reinterpret_cast<const float4*>(s_in + SW(base + j));
            P1_STEP(v.x, p[j + 0]); P1_STEP(v.y, p[j + 1]);
            P1_STEP(v.z, p[j + 2]); P1_STEP(v.w, p[j + 3]);
        }
        f.x = y_1; f.y = y_2;
    }

    // ---- history: warp 0 filters 8 chunks covering [S0-256, S0) ----
    if (warp == 0) {
        const int k    = lane & (NHIST - 1);
        const int base = 4 + k * CH;
        float x_1 = s_in[SW(base - 1)];
        float x_2 = s_in[SW(base - 2)];
        float y_1 = 0.0f, y_2 = 0.0f;
        float dummy;
        #pragma unroll
        for (int j = 0; j < CH; j += 4) {
            float4 v = *reinterpret_cast<const float4*>(s_in + SW(base + j));
            P1_STEP(v.x, dummy); P1_STEP(v.y, dummy);
            P1_STEP(v.z, dummy); P1_STEP(v.w, dummy);
        }
        (void)dummy;
        float2 fh = make_float2(y_1, y_2);
        float2 s  = make_float2(0.f, 0.f);            // zero state 256 back (~1e-11)
        #pragma unroll
        for (int q = 0; q < NHIST; q++) {             // compose in time order
            float fx = __shfl_sync(0xffffffffu, fh.x, q);
            float fy = __shfl_sync(0xffffffffu, fh.y, q);
            float sx = fmaf(A32.a, s.x, fmaf(A32.b, s.y, fx));
            float sy = fmaf(A32.c, s.x, fmaf(A32.d, s.y, fy));
            s.x = sx; s.y = sy;
        }
        if (lane == 0) scF[NWARP] = s;                // block incoming state
    }

    // ---- within-warp inclusive affine scan + per-thread V = A^(32*lane) ----
    float2 P = f;
    M2 L = A32;                                       // level matrix A^(32*2^k)
    M2 V; V.a = 1.0f; V.b = 0.0f; V.c = 0.0f; V.d = 1.0f;
    #pragma unroll
    for (int k = 0; k < 5; k++) {
        const int d = 1 << k;
        float px = __shfl_up_sync(0xffffffffu, P.x, d);
        float py = __shfl_up_sync(0xffffffffu, P.y, d);
        if (lane >= d) {                              // suffix length == d here
            P.x = fmaf(L.a, px, fmaf(L.b, py, P.x));
            P.y = fmaf(L.c, px, fmaf(L.d, py, P.y));
        }
        if ((lane >> k) & 1) V = mmul(L, V);          // build A^(32*lane)
        L = msq(L);
    }
    // L = A^1024 (warp span). Publish warp aggregates.
    if (lane == 31) scF[warp] = P;
    __syncthreads();                                  // the one block barrier

    // ---- incoming state of my warp's 1024-sample segment ----
    float2 W = scF[NWARP];                            // = s_blk
    #pragma unroll
    for (int w2 = 0; w2 < NWARP - 1; w2++) {
        if (w2 < warp) {
            float2 Fw = scF[w2];
            float wx = fmaf(L.a, W.x, fmaf(L.b, W.y, Fw.x));
            float wy = fmaf(L.c, W.x, fmaf(L.d, W.y, Fw.y));
            W.x = wx; W.y = wy;
        }
    }

    // ---- exact incoming state of my chunk: delta = V*W + Q (exclusive offset) ----
    float Qx = __shfl_up_sync(0xffffffffu, P.x, 1);
    float Qy = __shfl_up_sync(0xffffffffu, P.y, 1);
    if (lane == 0) { Qx = 0.0f; Qy = 0.0f; }
    float2 delta;
    delta.x = fmaf(V.a, W.x, fmaf(V.b, W.y, Qx));
    delta.y = fmaf(V.c, W.x, fmaf(V.d, W.y, Qy));

    // ---- pass 2: homogeneous correction, write into reused s_in (own warp seg) ----
    {
        float h1 = delta.x, h2 = delta.y;
        const int ob = tid * CH;
        #pragma unroll
        for (int j = 0; j < CH; j += 4) {
            float4 o;
            float hA = fmaf(na1, h1, na2 * h2);
            float hB = fmaf(na1, hA, na2 * h1);
            float hC = fmaf(na1, hB, na2 * hA);
            float hD = fmaf(na1, hC, na2 * hB);
            o.x = p[j + 0] + hA; o.y = p[j + 1] + hB;
            o.z = p[j + 2] + hC; o.w = p[j + 3] + hD;
            h2 = hC; h1 = hD;
            *reinterpret_cast<float4*>(s_in + SW(ob + j)) = o;
        }
    }
    __syncwarp();     // warp's 1024-word output segment written only by this warp

    // ---- drain: each warp drains its own segment, streaming stores ----
    {
        const int wbase = warp * 1024;
        #pragma unroll
        for (int m = 0; m < 8; m++) {
            const int w = wbase + 4 * (m * 32 + lane);
            float4 v = *reinterpret_cast<const float4*>(s_in + SW(w));
            __stcs(reinterpret_cast<float4*>(orow + S0 + w), v);
        }
    }
    #undef P1_STEP
}

extern "C" void kernel_launch(void* const* d_in, const int* in_sizes, int n_in,
                              void* d_out, int out_size)
{
    const float* x    = (const float*)d_in[0];
    const float* cf   = (const float*)d_in[1];
    const float* bw   = (const float*)d_in[2];
    const float* gain = (const float*)d_in[3];
    const int*   sr   = (const int*)  d_in[4];
    float*       out  = (float*)d_out;

    const int B = 128;
    const int T = in_sizes[0] / B;                 // 262144
    const int blocks_per_row = T / SPAN;           // 64
    const int grid = B * blocks_per_row;           // 8192

    cudaFuncSetAttribute(bandpass_kernel,
                         cudaFuncAttributeMaxDynamicSharedMemorySize, SMEM_BYTES);
    bandpass_kernel<<<grid, BLOCK, SMEM_BYTES>>>(x, cf, bw, gain, sr, out,
                                                 T, blocks_per_row);
}

// round 16
// speedup vs baseline: 1.3899x; 1.3899x over previous
#include <cuda_runtime.h>
#include <cstdint>

// Bandpass biquad (HP1 x LP1), B=128 rows, T=262144. Exact block-level scan
// (R11 champion structure). Single tile per block (regs<=64 -> 8 blocks/SM),
// cp.async fill (one wait point), per-warp drain. Only change vs R11:
// streaming (__stcs) drain stores — output is never re-read, keep L2 for
// the input regions that neighboring blocks' history fills re-touch.

static constexpr int BLOCK = 128;
static constexpr int CH    = 32;                  // owned samples / thread
static constexpr int NHIST = 8;                   // 8*32 = 256-sample history
static constexpr int SPAN  = BLOCK * CH;          // 4096
static constexpr int PRE   = NHIST * CH + 4;      // 260
static constexpr int IN_WORDS = SPAN + PRE;       // 4356
static constexpr int NWARP = BLOCK / 32;          // 4
static constexpr int SMEM_BYTES = IN_WORDS * 4 + (NWARP + 1) * sizeof(float2);

// 16B-granular bank swizzle for stride-32 accesses (pure permutation).
#define SW(w) ((w) ^ ((((w) >> 5) & 7) << 2))

struct M2 { float a, b, c, d; };                  // [[a,b],[c,d]]
__device__ __forceinline__ M2 msq(M2 m) {
    M2 r;
    r.a = fmaf(m.a, m.a, m.b * m.c);
    r.b = fmaf(m.a, m.b, m.b * m.d);
    r.c = fmaf(m.c, m.a, m.d * m.c);
    r.d = fmaf(m.c, m.b, m.d * m.d);
    return r;
}
__device__ __forceinline__ M2 mmul(M2 p, M2 q) {  // p*q
    M2 r;
    r.a = fmaf(p.a, q.a, p.b * q.c);
    r.b = fmaf(p.a, q.b, p.b * q.d);
    r.c = fmaf(p.c, q.a, p.d * q.c);
    r.d = fmaf(p.c, q.b, p.d * q.d);
    return r;
}

__device__ __forceinline__ void cpa16(uint32_t daddr, const void* src) {
    asm volatile("cp.async.cg.shared.global [%0], [%1], 16;\n"
                 :: "r"(daddr), "l"(src) : "memory");
}

__global__ __launch_bounds__(BLOCK)
void bandpass_kernel(const float* __restrict__ x,
                     const float* __restrict__ p_cf,
                     const float* __restrict__ p_bw,
                     const float* __restrict__ p_gain,
                     const int*   __restrict__ p_sr,
                     float* __restrict__ out,
                     int T, int blocks_per_row)
{
    extern __shared__ float smem[];
    float*  __restrict__ s_in = smem;                          // IN_WORDS
    float2* __restrict__ scF  = (float2*)(smem + IN_WORDS);    // [0..3]=warp agg, [4]=s_blk
    const uint32_t smem_cvta = (uint32_t)__cvta_generic_to_shared(smem);

    const int tid  = threadIdx.x;
    const int lane = tid & 31;
    const int warp = tid >> 5;
    const int row  = blockIdx.x / blocks_per_row;
    const int sblk = blockIdx.x - row * blocks_per_row;
    const int S0   = sblk * SPAN;

    const float* __restrict__ xr   = x   + (size_t)row * T;
    float* __restrict__       orow = out + (size_t)row * T;

    // ---- fill: cp.async load of [S0-PRE, S0+SPAN), zeros before row start ----
    {
        const int total4 = IN_WORDS / 4;                       // 1089
        #pragma unroll
        for (int m = 0; m < (IN_WORDS / 4 + BLOCK - 1) / BLOCK; m++) {
            const int idx = m * BLOCK + tid;
            if (idx < total4) {
                const int e = S0 - PRE + 4 * idx;
                const uint32_t daddr = smem_cvta + 4u * (uint32_t)SW(4 * idx);
                if (e >= 0) {
                    cpa16(daddr, xr + e);
                } else {
                    asm volatile("st.shared.v4.b32 [%0], {%1,%1,%1,%1};"
                                 :: "r"(daddr), "r"(0) : "memory");
                }
            }
        }
        asm volatile("cp.async.commit_group;" ::: "memory");
    }

    // ---- coefficients while the fill flies ----
    const float cf   = *p_cf;
    const float bw   = *p_bw;
    const float gain = *p_gain;
    const float nyq  = 0.5f * (float)(*p_sr);
    const float PI_  = 3.14159265358979323846f;

    const float Kh  = tanf(PI_ * ((cf - 0.5f * bw) / nyq) * 0.5f);
    const float ah1 = (Kh - 1.0f) / (Kh + 1.0f);
    const float bh0 = 1.0f / (Kh + 1.0f);
    const float Kl  = tanf(PI_ * ((cf + 0.5f * bw) / nyq) * 0.5f);
    const float al1 = (Kl - 1.0f) / (Kl + 1.0f);
    const float bl0 = Kl / (Kl + 1.0f);

    const float na1 = -(ah1 + al1);   // y = na1*y1 + na2*y2 + gg*(x - x2)
    const float na2 = -(ah1 * al1);
    const float gg  = bh0 * bl0 * gain;

    M2 A32; { M2 A; A.a = na1; A.b = na2; A.c = 1.0f; A.d = 0.0f;
              A32 = msq(A); A32 = msq(A32); A32 = msq(A32);
              A32 = msq(A32); A32 = msq(A32); }

    asm volatile("cp.async.wait_group 0;" ::: "memory");
    __syncthreads();

    // one zero-y-state filter step (exact x history)
    #define P1_STEP(XC, PJ)                           \
        {                                             \
            float u_  = gg * ((XC) - x_2);            \
            float t0_ = fmaf(na2, y_2, u_);           \
            float yn_ = fmaf(na1, y_1, t0_);          \
            x_2 = x_1; x_1 = (XC);                    \
            y_2 = y_1; y_1 = yn_;                     \
            (PJ) = yn_;                               \
        }

    // ---- pass 1: particular solution of own chunk, zero incoming y-state ----
    float p[CH];
    float2 f;
    {
        const int base = PRE + tid * CH;
        float x_1 = s_in[SW(base - 1)];
        float x_2 = s_in[SW(base - 2)];
        float y_1 = 0.0f, y_2 = 0.0f;
        #pragma unroll
        for (int j = 0; j < CH; j += 4) {
            float4 v = *reinterpret_cast<const float4*>(s_in + SW(base + j));
            P1_STEP(v.x, p[j + 0]); P1_STEP(v.y, p[j + 1]);
            P1_STEP(v.z, p[j + 2]); P1_STEP(v.w, p[j + 3]);
        }
        f.x = y_1; f.y = y_2;
    }

    // ---- history: warp 0 filters 8 chunks covering [S0-256, S0) ----
    if (tid < 32) {
        const int k    = lane & (NHIST - 1);
        const int base = 4 + k * CH;
        float x_1 = s_in[SW(base - 1)];
        float x_2 = s_in[SW(base - 2)];
        float y_1 = 0.0f, y_2 = 0.0f;
        float dummy;
        #pragma unroll
        for (int j = 0; j < CH; j += 4) {
            float4 v = *reinterpret_cast<const float4*>(s_in + SW(base + j));
            P1_STEP(v.x, dummy); P1_STEP(v.y, dummy);
            P1_STEP(v.z, dummy); P1_STEP(v.w, dummy);
        }
        (void)dummy;
        float2 fh = make_float2(y_1, y_2);
        float2 s  = make_float2(0.f, 0.f);            // zero state 256 back (~1e-11)
        #pragma unroll
        for (int q = 0; q < NHIST; q++) {             // compose in time order
            float fx = __shfl_sync(0xffffffffu, fh.x, q);
            float fy = __shfl_sync(0xffffffffu, fh.y, q);
            float sx = fmaf(A32.a, s.x, fmaf(A32.b, s.y, fx));
            float sy = fmaf(A32.c, s.x, fmaf(A32.d, s.y, fy));
            s.x = sx; s.y = sy;
        }
        if (lane == 0) scF[NWARP] = s;                // block incoming state
    }

    // ---- within-warp inclusive affine scan + per-thread V = A^(32*lane) ----
    float2 P = f;
    M2 L = A32;                                       // level matrix A^(32*2^k)
    M2 V; V.a = 1.0f; V.b = 0.0f; V.c = 0.0f; V.d = 1.0f;
    #pragma unroll
    for (int k = 0; k < 5; k++) {
        const int d = 1 << k;
        float px = __shfl_up_sync(0xffffffffu, P.x, d);
        float py = __shfl_up_sync(0xffffffffu, P.y, d);
        if (lane >= d) {                              // suffix length == d here
            P.x = fmaf(L.a, px, fmaf(L.b, py, P.x));
            P.y = fmaf(L.c, px, fmaf(L.d, py, P.y));
        }
        if ((lane >> k) & 1) V = mmul(L, V);          // build A^(32*lane)
        L = msq(L);
    }
    // L = A^1024 (warp span). Publish warp aggregates.
    if (lane == 31) scF[warp] = P;
    __syncthreads();

    // ---- incoming state of my warp's 1024-sample segment ----
    float2 W = scF[NWARP];                            // = s_blk
    #pragma unroll
    for (int w2 = 0; w2 < NWARP - 1; w2++) {
        if (w2 < warp) {
            float2 Fw = scF[w2];
            float wx = fmaf(L.a, W.x, fmaf(L.b, W.y, Fw.x));
            float wy = fmaf(L.c, W.x, fmaf(L.d, W.y, Fw.y));
            W.x = wx; W.y = wy;
        }
    }

    // ---- exact incoming state of my chunk: delta = V*W + Q (exclusive offset) ----
    float Qx = __shfl_up_sync(0xffffffffu, P.x, 1);
    float Qy = __shfl_up_sync(0xffffffffu, P.y, 1);
    if (lane == 0) { Qx = 0.0f; Qy = 0.0f; }
    float2 delta;
    delta.x = fmaf(V.a, W.x, fmaf(V.b, W.y, Qx));
    delta.y = fmaf(V.c, W.x, fmaf(V.d, W.y, Qy));

    // ---- pass 2: homogeneous correction, write into reused s_in (own warp seg) ----
    {
        float h1 = delta.x, h2 = delta.y;
        const int ob = tid * CH;
        #pragma unroll
        for (int j = 0; j < CH; j += 4) {
            float4 o;
            float hA = fmaf(na1, h1, na2 * h2);
            float hB = fmaf(na1, hA, na2 * h1);
            float hC = fmaf(na1, hB, na2 * hA);
            float hD = fmaf(na1, hC, na2 * hB);
            o.x = p[j + 0] + hA; o.y = p[j + 1] + hB;
            o.z = p[j + 2] + hC; o.w = p[j + 3] + hD;
            h2 = hC; h1 = hD;
            *reinterpret_cast<float4*>(s_in + SW(ob + j)) = o;
        }
    }
    __syncwarp();     // warp's 1024-word segment written only by this warp

    // ---- drain: each warp drains its own 1024-word segment, streaming stores ----
    {
        const int wbase = warp * 1024;
        #pragma unroll
        for (int m = 0; m < 8; m++) {
            const int w = wbase + 4 * (m * 32 + lane);
            float4 v = *reinterpret_cast<const float4*>(s_in + SW(w));
            __stcs(reinterpret_cast<float4*>(orow + S0 + w), v);
        }
    }
    #undef P1_STEP
}

extern "C" void kernel_launch(void* const* d_in, const int* in_sizes, int n_in,
                              void* d_out, int out_size)
{
    const float* x    = (const float*)d_in[0];
    const float* cf   = (const float*)d_in[1];
    const float* bw   = (const float*)d_in[2];
    const float* gain = (const float*)d_in[3];
    const int*   sr   = (const int*)  d_in[4];
    float*       out  = (float*)d_out;

    const int B = 128;
    const int T = in_sizes[0] / B;                 // 262144
    const int blocks_per_row = T / SPAN;           // 64
    const int grid = B * blocks_per_row;           // 8192

    cudaFuncSetAttribute(bandpass_kernel,
                         cudaFuncAttributeMaxDynamicSharedMemorySize, SMEM_BYTES);
    bandpass_kernel<<<grid, BLOCK, SMEM_BYTES>>>(x, cf, bw, gain, sr, out,
                                                 T, blocks_per_row);
}

// round 17
// speedup vs baseline: 1.4025x; 1.0091x over previous
#include <cuda_runtime.h>
#include <cstdint>

// Bandpass biquad (HP1 x LP1 collapsed), B=128 rows, T=262144.
// FINAL (R11 champion, re-confirmed): exact block-level affine scan.
//   fill:   cp.async gmem -> swizzled smem span [S0-260, S0+4096), one wait
//   pass1:  128 threads x 32-sample chunks from zero y-state (exact x hist),
//           outputs in registers, final state f
//   hist:   warp 0 filters 8x32 history chunks (residual ~1e-11), composes
//           the block's incoming state
//   scan:   within-warp inclusive affine scan with uniform level matrices
//           (valid under lane>=d guard) + per-thread V=A^(32*lane) +
//           serial 4-warp aggregate composition -> exact per-chunk state
//   pass2:  homogeneous correction added to register outputs, written to
//           reused smem (own warp segment only -> __syncwarp suffices)
//   drain:  per-warp coalesced smem -> gmem

static constexpr int BLOCK = 128;
static constexpr int CH    = 32;                  // owned samples / thread
static constexpr int NHIST = 8;                   // 8*32 = 256-sample history
static constexpr int SPAN  = BLOCK * CH;          // 4096
static constexpr int PRE   = NHIST * CH + 4;      // 260
static constexpr int IN_WORDS = SPAN + PRE;       // 4356
static constexpr int NWARP = BLOCK / 32;          // 4
static constexpr int SMEM_BYTES = IN_WORDS * 4 + (NWARP + 1) * sizeof(float2);

// 16B-granular bank swizzle for stride-32 accesses (pure permutation).
#define SW(w) ((w) ^ ((((w) >> 5) & 7) << 2))

struct M2 { float a, b, c, d; };                  // [[a,b],[c,d]]
__device__ __forceinline__ M2 msq(M2 m) {
    M2 r;
    r.a = fmaf(m.a, m.a, m.b * m.c);
    r.b = fmaf(m.a, m.b, m.b * m.d);
    r.c = fmaf(m.c, m.a, m.d * m.c);
    r.d = fmaf(m.c, m.b, m.d * m.d);
    return r;
}
__device__ __forceinline__ M2 mmul(M2 p, M2 q) {  // p*q
    M2 r;
    r.a = fmaf(p.a, q.a, p.b * q.c);
    r.b = fmaf(p.a, q.b, p.b * q.d);
    r.c = fmaf(p.c, q.a, p.d * q.c);
    r.d = fmaf(p.c, q.b, p.d * q.d);
    return r;
}

__device__ __forceinline__ void cpa16(uint32_t daddr, const void* src) {
    asm volatile("cp.async.cg.shared.global [%0], [%1], 16;\n"
                 :: "r"(daddr), "l"(src) : "memory");
}

__global__ __launch_bounds__(BLOCK)
void bandpass_kernel(const float* __restrict__ x,
                     const float* __restrict__ p_cf,
                     const float* __restrict__ p_bw,
                     const float* __restrict__ p_gain,
                     const int*   __restrict__ p_sr,
                     float* __restrict__ out,
                     int T, int blocks_per_row)
{
    extern __shared__ float smem[];
    float*  __restrict__ s_in = smem;                          // IN_WORDS
    float2* __restrict__ scF  = (float2*)(smem + IN_WORDS);    // [0..3]=warp agg, [4]=s_blk
    const uint32_t smem_cvta = (uint32_t)__cvta_generic_to_shared(smem);

    const int tid  = threadIdx.x;
    const int lane = tid & 31;
    const int warp = tid >> 5;
    const int row  = blockIdx.x / blocks_per_row;
    const int sblk = blockIdx.x - row * blocks_per_row;
    const int S0   = sblk * SPAN;

    const float* __restrict__ xr   = x   + (size_t)row * T;
    float* __restrict__       orow = out + (size_t)row * T;

    // ---- fill: cp.async load of [S0-PRE, S0+SPAN), zeros before row start ----
    {
        const int total4 = IN_WORDS / 4;                       // 1089
        #pragma unroll
        for (int m = 0; m < (IN_WORDS / 4 + BLOCK - 1) / BLOCK; m++) {
            const int idx = m * BLOCK + tid;
            if (idx < total4) {
                const int e = S0 - PRE + 4 * idx;
                const uint32_t daddr = smem_cvta + 4u * (uint32_t)SW(4 * idx);
                if (e >= 0) {
                    cpa16(daddr, xr + e);
                } else {
                    asm volatile("st.shared.v4.b32 [%0], {%1,%1,%1,%1};"
                                 :: "r"(daddr), "r"(0) : "memory");
                }
            }
        }
        asm volatile("cp.async.commit_group;" ::: "memory");
    }

    // ---- coefficients while the fill flies ----
    const float cf   = *p_cf;
    const float bw   = *p_bw;
    const float gain = *p_gain;
    const float nyq  = 0.5f * (float)(*p_sr);
    const float PI_  = 3.14159265358979323846f;

    const float Kh  = tanf(PI_ * ((cf - 0.5f * bw) / nyq) * 0.5f);
    const float ah1 = (Kh - 1.0f) / (Kh + 1.0f);
    const float bh0 = 1.0f / (Kh + 1.0f);
    const float Kl  = tanf(PI_ * ((cf + 0.5f * bw) / nyq) * 0.5f);
    const float al1 = (Kl - 1.0f) / (Kl + 1.0f);
    const float bl0 = Kl / (Kl + 1.0f);

    const float na1 = -(ah1 + al1);   // y = na1*y1 + na2*y2 + gg*(x - x2)
    const float na2 = -(ah1 * al1);
    const float gg  = bh0 * bl0 * gain;

    M2 A32; { M2 A; A.a = na1; A.b = na2; A.c = 1.0f; A.d = 0.0f;
              A32 = msq(A); A32 = msq(A32); A32 = msq(A32);
              A32 = msq(A32); A32 = msq(A32); }

    asm volatile("cp.async.wait_group 0;" ::: "memory");
    __syncthreads();

    // one zero-y-state filter step (exact x history)
    #define P1_STEP(XC, PJ)                           \
        {                                             \
            float u_  = gg * ((XC) - x_2);            \
            float t0_ = fmaf(na2, y_2, u_);           \
            float yn_ = fmaf(na1, y_1, t0_);          \
            x_2 = x_1; x_1 = (XC);                    \
            y_2 = y_1; y_1 = yn_;                     \
            (PJ) = yn_;                               \
        }

    // ---- pass 1: particular solution of own chunk, zero incoming y-state ----
    float p[CH];
    float2 f;
    {
        const int base = PRE + tid * CH;
        float x_1 = s_in[SW(base - 1)];
        float x_2 = s_in[SW(base - 2)];
        float y_1 = 0.0f, y_2 = 0.0f;
        #pragma unroll
        for (int j = 0; j < CH; j += 4) {
            float4 v = *reinterpret_cast<const float4*>(s_in + SW(base + j));
            P1_STEP(v.x, p[j + 0]); P1_STEP(v.y, p[j + 1]);
            P1_STEP(v.z, p[j + 2]); P1_STEP(v.w, p[j + 3]);
        }
        f.x = y_1; f.y = y_2;
    }

    // ---- history: warp 0 filters 8 chunks covering [S0-256, S0) ----
    if (tid < 32) {
        const int k    = lane & (NHIST - 1);
        const int base = 4 + k * CH;
        float x_1 = s_in[SW(base - 1)];
        float x_2 = s_in[SW(base - 2)];
        float y_1 = 0.0f, y_2 = 0.0f;
        float dummy;
        #pragma unroll
        for (int j = 0; j < CH; j += 4) {
            float4 v = *reinterpret_cast<const float4*>(s_in + SW(base + j));
            P1_STEP(v.x, dummy); P1_STEP(v.y, dummy);
            P1_STEP(v.z, dummy); P1_STEP(v.w, dummy);
        }
        (void)dummy;
        float2 fh = make_float2(y_1, y_2);
        float2 s  = make_float2(0.f, 0.f);            // zero state 256 back (~1e-11)
        #pragma unroll
        for (int q = 0; q < NHIST; q++) {             // compose in time order
            float fx = __shfl_sync(0xffffffffu, fh.x, q);
            float fy = __shfl_sync(0xffffffffu, fh.y, q);
            float sx = fmaf(A32.a, s.x, fmaf(A32.b, s.y, fx));
            float sy = fmaf(A32.c, s.x, fmaf(A32.d, s.y, fy));
            s.x = sx; s.y = sy;
        }
        if (lane == 0) scF[NWARP] = s;                // block incoming state
    }

    // ---- within-warp inclusive affine scan + per-thread V = A^(32*lane) ----
    float2 P = f;
    M2 L = A32;                                       // level matrix A^(32*2^k)
    M2 V; V.a = 1.0f; V.b = 0.0f; V.c = 0.0f; V.d = 1.0f;
    #pragma unroll
    for (int k = 0; k < 5; k++) {
        const int d = 1 << k;
        float px = __shfl_up_sync(0xffffffffu, P.x, d);
        float py = __shfl_up_sync(0xffffffffu, P.y, d);
        if (lane >= d) {                              // suffix length == d here
            P.x = fmaf(L.a, px, fmaf(L.b, py, P.x));
            P.y = fmaf(L.c, px, fmaf(L.d, py, P.y));
        }
        if ((lane >> k) & 1) V = mmul(L, V);          // build A^(32*lane)
        L = msq(L);
    }
    // L = A^1024 (warp span). Publish warp aggregates.
    if (lane == 31) scF[warp] = P;
    __syncthreads();

    // ---- incoming state of my warp's 1024-sample segment ----
    float2 W = scF[NWARP];                            // = s_blk
    #pragma unroll
    for (int w2 = 0; w2 < NWARP - 1; w2++) {
        if (w2 < warp) {
            float2 Fw = scF[w2];
            float wx = fmaf(L.a, W.x, fmaf(L.b, W.y, Fw.x));
            float wy = fmaf(L.c, W.x, fmaf(L.d, W.y, Fw.y));
            W.x = wx; W.y = wy;
        }
    }

    // ---- exact incoming state of my chunk: delta = V*W + Q (exclusive offset) ----
    float Qx = __shfl_up_sync(0xffffffffu, P.x, 1);
    float Qy = __shfl_up_sync(0xffffffffu, P.y, 1);
    if (lane == 0) { Qx = 0.0f; Qy = 0.0f; }
    float2 delta;
    delta.x = fmaf(V.a, W.x, fmaf(V.b, W.y, Qx));
    delta.y = fmaf(V.c, W.x, fmaf(V.d, W.y, Qy));

    // ---- pass 2: homogeneous correction, write into reused s_in (own warp seg) ----
    {
        float h1 = delta.x, h2 = delta.y;
        const int ob = tid * CH;
        #pragma unroll
        for (int j = 0; j < CH; j += 4) {
            float4 o;
            float hA = fmaf(na1, h1, na2 * h2);
            float hB = fmaf(na1, hA, na2 * h1);
            float hC = fmaf(na1, hB, na2 * hA);
            float hD = fmaf(na1, hC, na2 * hB);
            o.x = p[j + 0] + hA; o.y = p[j + 1] + hB;
            o.z = p[j + 2] + hC; o.w = p[j + 3] + hD;
            h2 = hC; h1 = hD;
            *reinterpret_cast<float4*>(s_in + SW(ob + j)) = o;
        }
    }
    __syncwarp();     // warp's 1024-word segment written only by this warp

    // ---- drain: each warp drains its own 1024-word segment, coalesced ----
    {
        const int wbase = warp * 1024;
        #pragma unroll
        for (int m = 0; m < 8; m++) {
            const int w = wbase + 4 * (m * 32 + lane);
            float4 v = *reinterpret_cast<const float4*>(s_in + SW(w));
            *reinterpret_cast<float4*>(orow + S0 + w) = v;
        }
    }
    #undef P1_STEP
}

extern "C" void kernel_launch(void* const* d_in, const int* in_sizes, int n_in,
                              void* d_out, int out_size)
{
    const float* x    = (const float*)d_in[0];
    const float* cf   = (const float*)d_in[1];
    const float* bw   = (const float*)d_in[2];
    const float* gain = (const float*)d_in[3];
    const int*   sr   = (const int*)  d_in[4];
    float*       out  = (float*)d_out;

    const int B = 128;
    const int T = in_sizes[0] / B;                 // 262144
    const int blocks_per_row = T / SPAN;           // 64
    const int grid = B * blocks_per_row;           // 8192

    cudaFuncSetAttribute(bandpass_kernel,
                         cudaFuncAttributeMaxDynamicSharedMemorySize, SMEM_BYTES);
    bandpass_kernel<<<grid, BLOCK, SMEM_BYTES>>>(x, cf, bw, gain, sr, out,
                                                 T, blocks_per_row);
}